// round 16
// baseline (speedup 1.0000x reference)
#include <cuda_runtime.h>

#define BB 8192
#define DD 64
#define KK 32
#define HID 16

#define NC   128                  // cells per (k,d) column
#define XLO  (-6.0f)
#define INVD (128.0f / 12.0f)     // NC / 12
#define IOFF 64.0f                // -XLO * INVD (exact)
#define CW   (12.0f / 128.0f)     // cell width

#define DPB  8                    // d per main block
#define BSPL 8                    // b splits
#define BPB  (BB / BSPL)          // 1024 b per block
#define DG   (DD / DPB)           // 8 d-groups

// -------- device scratch --------
__device__ float2 g_tab[DD * NC * KK];          // 2 MB, layout [d][cell][k]
__device__ float  g_part[DG * BB * KK];         // 8 MB, [dg][b][k]
__device__ float  g_oPack[KK * 32];             // outer: [0:16)=A, [16:32)=t
__device__ float  g_oL[KK];
__device__ float  g_oC[KK];

// ---------------------------------------------------------------------------
// Prep: block per d (64 blocks), 512 threads = one per (k,h).
// f(x) = sum_h A_h*max(x,t_h) + L*x + C; sorted knots -> 17 segments:
//   S_j = L + sum_{i<j} A_(i) ;  B_j = C + sum_{i>=j} P_(i),  P = A*t exact.
// ALL per-lane-k smem rows use pitch 17 (odd): lane-indexed row access is a
// bank permutation -> conflict-free (the [32][16] pitch was a 16-way
// conflict on every fill-scan load).
// ---------------------------------------------------------------------------
__global__ void __launch_bounds__(512, 2)
kan_prep(const float* __restrict__ iw1, const float* __restrict__ ib1,
         const float* __restrict__ iw2, const float* __restrict__ ib2,
         const float* __restrict__ ow1, const float* __restrict__ ob1,
         const float* __restrict__ ow2, const float* __restrict__ ob2) {
    __shared__ float sT0[32][17];
    __shared__ float sTs[32][17], sS[32][17], sB[32][17];
    __shared__ float sL[32], sC[32];
    const int d = blockIdx.x;
    const int t = threadIdx.x;        // 512
    const int k = t >> 4, h = t & 15;

    // per-element transform (coalesced: h contiguous)
    const long base = ((long)k * DD + d) * HID + h;
    float a = iw1[base], b = ib1[base], c = iw2[base];
    float ac = a * c;
    float A, T, P, Lc = 0.f, Cc = 0.f;
    if (a > 0.f)      { A =  ac; T = __fdividef(-b, a); P = -c * b; Cc = c * b; }
    else if (a < 0.f) { A = -ac; T = __fdividef(-b, a); P =  c * b; Lc = ac; }
    else              { A = 0.f; T = 0.f;               P = 0.f;    Cc = c * fmaxf(b, 0.f); }
    sT0[k][h] = T;

    // reduce L, C over h (width-16 groups align with k)
#pragma unroll
    for (int o = 8; o > 0; o >>= 1) {
        Lc += __shfl_xor_sync(0xffffffffu, Lc, o, 16);
        Cc += __shfl_xor_sync(0xffffffffu, Cc, o, 16);
    }
    if (h == 0) { sL[k] = Lc; sC[k] = Cc + ib2[k * DD + d]; }
    __syncthreads();

    // parallel rank + scatter (sT0 reads are same-k broadcast within groups)
    {
        int r = 0;
#pragma unroll
        for (int j = 0; j < 16; j++) {
            float Tj = sT0[k][j];
            r += (Tj < T) || (Tj == T && j < h);
        }
        sTs[k][r] = T;
        sS[k][r]  = A;    // slopes by rank (pre-prefix)
        sB[k][r]  = P;    // P by rank (pre-prefix)
    }
    __syncthreads();

    // serial prefixes (trivial): S ascending from L, B descending from C
    if (t < 32) {
        const int kk = t;
        float run = sL[kk];
#pragma unroll
        for (int j = 0; j <= 16; j++) {
            float aj = (j < 16) ? sS[kk][j] : 0.f;
            sS[kk][j] = run;
            run += aj;
        }
        float run2 = sC[kk];
        sB[kk][16] = run2;
#pragma unroll
        for (int j = 15; j >= 0; j--) {
            float pj = sB[kk][j];
            run2 += pj;
            sB[kk][j] = run2;
        }
    }

    // outer-net transform (exact): block 0, threads 32..63
    if (blockIdx.x == 0 && t >= 32 && t < 64) {
        const int kk = t - 32;
        float Lo = 0.f, Co = ob2[kk];
#pragma unroll
        for (int hh = 0; hh < HID; hh++) {
            float aa = ow1[kk * HID + hh], bb = ob1[kk * HID + hh], cc = ow2[kk * HID + hh];
            float aacc = aa * cc, A2, tt;
            if (aa > 0.f)      { A2 = aacc;  tt = -bb / aa; Co += cc * bb; }
            else if (aa < 0.f) { A2 = -aacc; tt = -bb / aa; Lo += aacc; }
            else               { A2 = 0.f;   tt = 0.f;      Co += cc * fmaxf(bb, 0.f); }
            g_oPack[kk * 32 + hh]      = A2;
            g_oPack[kk * 32 + 16 + hh] = tt;
        }
        g_oL[kk] = Lo;
        g_oC[kk] = Co;
    }
    __syncthreads();

    // fill: entry e = (cell c, k); lane k + pitch 17 -> conflict-free scans;
    // writes coalesced (k contiguous)
#pragma unroll
    for (int e = t; e < NC * KK; e += 512) {    // 8 iters
        int cc = e >> 5, kk = e & 31;
        float m = XLO + (cc + 0.5f) * CW;
        int j = 0;
#pragma unroll
        for (int i = 0; i < 16; i++) j += (sTs[kk][i] <= m) ? 1 : 0;
        g_tab[((long)d * NC + cc) * KK + kk] = make_float2(sS[kk][j], sB[kk][j]);
    }
}

// ---------------------------------------------------------------------------
// Main: grid (8 bs, 8 dg, 2 kg) = 128 blocks, 512 threads, 160 KB smem.
// x staged in-kernel (per b: one 32B-aligned 32B slice). Lane = (half: b
// parity, kl: k within 16-group). Table LDS rows are contiguous 128B per
// half-warp -> deterministic conflict-free.
// ---------------------------------------------------------------------------
__global__ void __launch_bounds__(512, 1)
kan_main(const float* __restrict__ x) {
    extern __shared__ float smem[];
    float2* stab = (float2*)smem;                   // DPB*NC*16 float2 = 128 KB
    float*  sxb  = smem + DPB * NC * 16 * 2;        // DPB*BPB floats  = 32 KB

    const int t  = threadIdx.x;
    const int bs = blockIdx.x, dg = blockIdx.y, kg = blockIdx.z;
    const int d0 = dg * DPB, b0 = bs * BPB;

    // stage table slab (k-half): 8192 float4
    {
        const float4* gt = (const float4*)g_tab;    // float4 = 2 float2 entries
        float4* st = (float4*)stab;
#pragma unroll
        for (int i = 0; i < 16; i++) {
            int e  = t + i * 512;
            int q  = e & 7;
            int c  = (e >> 3) & (NC - 1);
            int dd = e >> 10;
            st[e] = gt[((long)(d0 + dd) * NC + c) * (KK / 2) + kg * 8 + q];
        }
    }
    // stage x chunk
    {
#pragma unroll
        for (int i = 0; i < BPB / 512; i++) {       // 2 iters
            int b = t + i * 512;
            const float4* xr = (const float4*)(x + (long)(b0 + b) * DD + d0);
            float4 v0 = xr[0], v1 = xr[1];
            sxb[0 * BPB + b] = v0.x;
            sxb[1 * BPB + b] = v0.y;
            sxb[2 * BPB + b] = v0.z;
            sxb[3 * BPB + b] = v0.w;
            sxb[4 * BPB + b] = v1.x;
            sxb[5 * BPB + b] = v1.y;
            sxb[6 * BPB + b] = v1.z;
            sxb[7 * BPB + b] = v1.w;
        }
    }
    __syncthreads();

    const int w    = t >> 5, l = t & 31;
    const int kl   = l & 15;
    const int half = l >> 4;
    const int kk   = kg * 16 + kl;
    float* pbase = g_part + ((long)dg * BB + b0) * KK;

#pragma unroll 2
    for (int p = w; p < BPB / 2; p += 16) {
        int b = 2 * p + half;
        float acc = 0.f;
#pragma unroll
        for (int dd = 0; dd < DPB; dd++) {
            float xx = sxb[dd * BPB + b];
            int i = (int)fmaf(xx, INVD, IOFF);
            i = i < 0 ? 0 : (i > NC - 1 ? NC - 1 : i);
            float2 sb = stab[(dd * NC + i) * 16 + kl];
            acc += fmaf(sb.x, xx, sb.y);
        }
        pbase[(long)b * KK + kk] = acc;
    }
}

// ---------------------------------------------------------------------------
// Out: thread-PAIR per (b, k-quad). Each thread sums 4 dg's (4 x LDG.128),
// pair combines via shfl_xor(1); even lane runs exact outer PWL + STG.128.
// ---------------------------------------------------------------------------
__global__ void kan_out(float* __restrict__ out) {
    __shared__ float sop[32 * 35];        // pitch 35: conflict-free
    const int t = threadIdx.x;
#pragma unroll
    for (int e = t; e < 1024; e += 256) sop[(e >> 5) * 35 + (e & 31)] = g_oPack[e];
    if (t < 32)       sop[t * 35 + 32] = g_oL[t];
    else if (t < 64)  sop[(t - 32) * 35 + 33] = g_oC[t - 32];
    __syncthreads();

    const int gid  = blockIdx.x * 256 + t;  // 0 .. BB*16-1
    const int half = gid & 1;
    const int oid  = gid >> 1;
    const int k4   = oid & 7;
    const int b    = oid >> 3;

    const float4* gp = (const float4*)g_part;
    float4 s = make_float4(0.f, 0.f, 0.f, 0.f);
#pragma unroll
    for (int j = 0; j < 4; j++) {
        int dg = half * 4 + j;
        float4 p = gp[((long)dg * BB + b) * (KK / 4) + k4];
        s.x += p.x; s.y += p.y; s.z += p.z; s.w += p.w;
    }
    s.x += __shfl_xor_sync(0xffffffffu, s.x, 1);
    s.y += __shfl_xor_sync(0xffffffffu, s.y, 1);
    s.z += __shfl_xor_sync(0xffffffffu, s.z, 1);
    s.w += __shfl_xor_sync(0xffffffffu, s.w, 1);

    if (half == 0) {
        float sk[4] = {s.x, s.y, s.z, s.w};
        float4 r4;
        float* rr = (float*)&r4;
#pragma unroll
        for (int j = 0; j < 4; j++) {
            const int k = k4 * 4 + j;
            const float* op = sop + k * 35;
            float sv = sk[j];
            float r = fmaf(op[32], sv, op[33]);
#pragma unroll
            for (int h = 0; h < HID; h++)
                r = fmaf(op[h], fmaxf(sv, op[16 + h]), r);
            rr[j] = r;
        }
        ((float4*)(out + (long)b * KK))[k4] = r4;
    }
}

// ---------------------------------------------------------------------------
extern "C" void kernel_launch(void* const* d_in, const int* in_sizes, int n_in,
                              void* d_out, int out_size) {
    const float* x   = (const float*)d_in[0];
    const float* iw1 = (const float*)d_in[1];
    const float* ib1 = (const float*)d_in[2];
    const float* iw2 = (const float*)d_in[3];
    const float* ib2 = (const float*)d_in[4];
    const float* ow1 = (const float*)d_in[5];
    const float* ob1 = (const float*)d_in[6];
    const float* ow2 = (const float*)d_in[7];
    const float* ob2 = (const float*)d_in[8];
    float* out = (float*)d_out;

    const int smem = (DPB * NC * 16 * 2 + DPB * BPB) * 4;   // 163840 B
    cudaFuncSetAttribute(kan_main, cudaFuncAttributeMaxDynamicSharedMemorySize, smem);

    kan_prep<<<DD, 512>>>(iw1, ib1, iw2, ib2, ow1, ob1, ow2, ob2);
    kan_main<<<dim3(BSPL, DG, 2), 512, smem>>>(x);
    kan_out<<<(BB * 16) / 256, 256>>>(out);
}

// round 17
// speedup vs baseline: 1.0119x; 1.0119x over previous
#include <cuda_runtime.h>

#define BB 8192
#define DD 64
#define KK 32
#define HID 16

#define NC   128                  // cells per (k,d) column
#define XLO  (-6.0f)
#define INVD (128.0f / 12.0f)     // NC / 12
#define IOFF 64.0f                // -XLO * INVD (exact)
#define CW   (12.0f / 128.0f)     // cell width

#define DPB  8                    // d per main block
#define BSPL 8                    // b splits
#define BPB  (BB / BSPL)          // 1024 b per block
#define DG   (DD / DPB)           // 8 d-groups

// -------- device scratch --------
__device__ float2 g_tab[DD * NC * KK];          // 2 MB, layout [d][cell][k]
__device__ float  g_part[DG * BB * KK];         // 8 MB, [dg][b][k]
__device__ float  g_oPack[KK * 32];             // outer: [0:16)=A, [16:32)=t
__device__ float  g_oL[KK];
__device__ float  g_oC[KK];

// ---------------------------------------------------------------------------
// Prep: block per d (64 blocks), 512 threads = one per (k,h).
// f(x) = sum_h A_h*max(x,t_h) + L*x + C; sorted knots -> 17 segments:
//   S_j = L + sum_{i<j} A_(i) ;  B_j = C + sum_{i>=j} P_(i),  P = A*t exact.
// ALL per-lane-k smem rows use pitch 17 (odd): lane-indexed row access is a
// bank permutation -> conflict-free (the [32][16] pitch was a 16-way
// conflict on every fill-scan load).
// ---------------------------------------------------------------------------
__global__ void __launch_bounds__(512, 2)
kan_prep(const float* __restrict__ iw1, const float* __restrict__ ib1,
         const float* __restrict__ iw2, const float* __restrict__ ib2,
         const float* __restrict__ ow1, const float* __restrict__ ob1,
         const float* __restrict__ ow2, const float* __restrict__ ob2) {
    __shared__ float sT0[32][17];
    __shared__ float sTs[32][17], sS[32][17], sB[32][17];
    __shared__ float sL[32], sC[32];
    const int d = blockIdx.x;
    const int t = threadIdx.x;        // 512
    const int k = t >> 4, h = t & 15;

    // per-element transform (coalesced: h contiguous)
    const long base = ((long)k * DD + d) * HID + h;
    float a = iw1[base], b = ib1[base], c = iw2[base];
    float ac = a * c;
    float A, T, P, Lc = 0.f, Cc = 0.f;
    if (a > 0.f)      { A =  ac; T = __fdividef(-b, a); P = -c * b; Cc = c * b; }
    else if (a < 0.f) { A = -ac; T = __fdividef(-b, a); P =  c * b; Lc = ac; }
    else              { A = 0.f; T = 0.f;               P = 0.f;    Cc = c * fmaxf(b, 0.f); }
    sT0[k][h] = T;

    // reduce L, C over h (width-16 groups align with k)
#pragma unroll
    for (int o = 8; o > 0; o >>= 1) {
        Lc += __shfl_xor_sync(0xffffffffu, Lc, o, 16);
        Cc += __shfl_xor_sync(0xffffffffu, Cc, o, 16);
    }
    if (h == 0) { sL[k] = Lc; sC[k] = Cc + ib2[k * DD + d]; }
    __syncthreads();

    // parallel rank + scatter (sT0 reads are same-k broadcast within groups)
    {
        int r = 0;
#pragma unroll
        for (int j = 0; j < 16; j++) {
            float Tj = sT0[k][j];
            r += (Tj < T) || (Tj == T && j < h);
        }
        sTs[k][r] = T;
        sS[k][r]  = A;    // slopes by rank (pre-prefix)
        sB[k][r]  = P;    // P by rank (pre-prefix)
    }
    __syncthreads();

    // serial prefixes (trivial): S ascending from L, B descending from C
    if (t < 32) {
        const int kk = t;
        float run = sL[kk];
#pragma unroll
        for (int j = 0; j <= 16; j++) {
            float aj = (j < 16) ? sS[kk][j] : 0.f;
            sS[kk][j] = run;
            run += aj;
        }
        float run2 = sC[kk];
        sB[kk][16] = run2;
#pragma unroll
        for (int j = 15; j >= 0; j--) {
            float pj = sB[kk][j];
            run2 += pj;
            sB[kk][j] = run2;
        }
    }

    // outer-net transform (exact): block 0, threads 32..63
    if (blockIdx.x == 0 && t >= 32 && t < 64) {
        const int kk = t - 32;
        float Lo = 0.f, Co = ob2[kk];
#pragma unroll
        for (int hh = 0; hh < HID; hh++) {
            float aa = ow1[kk * HID + hh], bb = ob1[kk * HID + hh], cc = ow2[kk * HID + hh];
            float aacc = aa * cc, A2, tt;
            if (aa > 0.f)      { A2 = aacc;  tt = -bb / aa; Co += cc * bb; }
            else if (aa < 0.f) { A2 = -aacc; tt = -bb / aa; Lo += aacc; }
            else               { A2 = 0.f;   tt = 0.f;      Co += cc * fmaxf(bb, 0.f); }
            g_oPack[kk * 32 + hh]      = A2;
            g_oPack[kk * 32 + 16 + hh] = tt;
        }
        g_oL[kk] = Lo;
        g_oC[kk] = Co;
    }
    __syncthreads();

    // fill: entry e = (cell c, k); lane k + pitch 17 -> conflict-free scans;
    // writes coalesced (k contiguous)
#pragma unroll
    for (int e = t; e < NC * KK; e += 512) {    // 8 iters
        int cc = e >> 5, kk = e & 31;
        float m = XLO + (cc + 0.5f) * CW;
        int j = 0;
#pragma unroll
        for (int i = 0; i < 16; i++) j += (sTs[kk][i] <= m) ? 1 : 0;
        g_tab[((long)d * NC + cc) * KK + kk] = make_float2(sS[kk][j], sB[kk][j]);
    }
}

// ---------------------------------------------------------------------------
// Main: grid (8 bs, 8 dg, 2 kg) = 128 blocks, 512 threads, 160 KB smem.
// x staged in-kernel (per b: one 32B-aligned 32B slice). Lane = (half: b
// parity, kl: k within 16-group). Table LDS rows are contiguous 128B per
// half-warp -> deterministic conflict-free.
// ---------------------------------------------------------------------------
__global__ void __launch_bounds__(512, 1)
kan_main(const float* __restrict__ x) {
    extern __shared__ float smem[];
    float2* stab = (float2*)smem;                   // DPB*NC*16 float2 = 128 KB
    float*  sxb  = smem + DPB * NC * 16 * 2;        // DPB*BPB floats  = 32 KB

    const int t  = threadIdx.x;
    const int bs = blockIdx.x, dg = blockIdx.y, kg = blockIdx.z;
    const int d0 = dg * DPB, b0 = bs * BPB;

    // stage table slab (k-half): 8192 float4
    {
        const float4* gt = (const float4*)g_tab;    // float4 = 2 float2 entries
        float4* st = (float4*)stab;
#pragma unroll
        for (int i = 0; i < 16; i++) {
            int e  = t + i * 512;
            int q  = e & 7;
            int c  = (e >> 3) & (NC - 1);
            int dd = e >> 10;
            st[e] = gt[((long)(d0 + dd) * NC + c) * (KK / 2) + kg * 8 + q];
        }
    }
    // stage x chunk
    {
#pragma unroll
        for (int i = 0; i < BPB / 512; i++) {       // 2 iters
            int b = t + i * 512;
            const float4* xr = (const float4*)(x + (long)(b0 + b) * DD + d0);
            float4 v0 = xr[0], v1 = xr[1];
            sxb[0 * BPB + b] = v0.x;
            sxb[1 * BPB + b] = v0.y;
            sxb[2 * BPB + b] = v0.z;
            sxb[3 * BPB + b] = v0.w;
            sxb[4 * BPB + b] = v1.x;
            sxb[5 * BPB + b] = v1.y;
            sxb[6 * BPB + b] = v1.z;
            sxb[7 * BPB + b] = v1.w;
        }
    }
    __syncthreads();

    const int w    = t >> 5, l = t & 31;
    const int kl   = l & 15;
    const int half = l >> 4;
    const int kk   = kg * 16 + kl;
    float* pbase = g_part + ((long)dg * BB + b0) * KK;

#pragma unroll 2
    for (int p = w; p < BPB / 2; p += 16) {
        int b = 2 * p + half;
        float acc = 0.f;
#pragma unroll
        for (int dd = 0; dd < DPB; dd++) {
            float xx = sxb[dd * BPB + b];
            int i = (int)fmaf(xx, INVD, IOFF);
            i = i < 0 ? 0 : (i > NC - 1 ? NC - 1 : i);
            float2 sb = stab[(dd * NC + i) * 16 + kl];
            acc += fmaf(sb.x, xx, sb.y);
        }
        pbase[(long)b * KK + kk] = acc;
    }
}

// ---------------------------------------------------------------------------
// Out: thread-PAIR per (b, k-quad). Each thread sums 4 dg's (4 x LDG.128),
// pair combines via shfl_xor(1); even lane runs exact outer PWL + STG.128.
// ---------------------------------------------------------------------------
__global__ void kan_out(float* __restrict__ out) {
    __shared__ float sop[32 * 35];        // pitch 35: conflict-free
    const int t = threadIdx.x;
#pragma unroll
    for (int e = t; e < 1024; e += 256) sop[(e >> 5) * 35 + (e & 31)] = g_oPack[e];
    if (t < 32)       sop[t * 35 + 32] = g_oL[t];
    else if (t < 64)  sop[(t - 32) * 35 + 33] = g_oC[t - 32];
    __syncthreads();

    const int gid  = blockIdx.x * 256 + t;  // 0 .. BB*16-1
    const int half = gid & 1;
    const int oid  = gid >> 1;
    const int k4   = oid & 7;
    const int b    = oid >> 3;

    const float4* gp = (const float4*)g_part;
    float4 s = make_float4(0.f, 0.f, 0.f, 0.f);
#pragma unroll
    for (int j = 0; j < 4; j++) {
        int dg = half * 4 + j;
        float4 p = gp[((long)dg * BB + b) * (KK / 4) + k4];
        s.x += p.x; s.y += p.y; s.z += p.z; s.w += p.w;
    }
    s.x += __shfl_xor_sync(0xffffffffu, s.x, 1);
    s.y += __shfl_xor_sync(0xffffffffu, s.y, 1);
    s.z += __shfl_xor_sync(0xffffffffu, s.z, 1);
    s.w += __shfl_xor_sync(0xffffffffu, s.w, 1);

    if (half == 0) {
        float sk[4] = {s.x, s.y, s.z, s.w};
        float4 r4;
        float* rr = (float*)&r4;
#pragma unroll
        for (int j = 0; j < 4; j++) {
            const int k = k4 * 4 + j;
            const float* op = sop + k * 35;
            float sv = sk[j];
            float r = fmaf(op[32], sv, op[33]);
#pragma unroll
            for (int h = 0; h < HID; h++)
                r = fmaf(op[h], fmaxf(sv, op[16 + h]), r);
            rr[j] = r;
        }
        ((float4*)(out + (long)b * KK))[k4] = r4;
    }
}

// ---------------------------------------------------------------------------
extern "C" void kernel_launch(void* const* d_in, const int* in_sizes, int n_in,
                              void* d_out, int out_size) {
    const float* x   = (const float*)d_in[0];
    const float* iw1 = (const float*)d_in[1];
    const float* ib1 = (const float*)d_in[2];
    const float* iw2 = (const float*)d_in[3];
    const float* ib2 = (const float*)d_in[4];
    const float* ow1 = (const float*)d_in[5];
    const float* ob1 = (const float*)d_in[6];
    const float* ow2 = (const float*)d_in[7];
    const float* ob2 = (const float*)d_in[8];
    float* out = (float*)d_out;

    const int smem = (DPB * NC * 16 * 2 + DPB * BPB) * 4;   // 163840 B
    cudaFuncSetAttribute(kan_main, cudaFuncAttributeMaxDynamicSharedMemorySize, smem);

    kan_prep<<<DD, 512>>>(iw1, ib1, iw2, ib2, ow1, ob1, ow2, ob2);
    kan_main<<<dim3(BSPL, DG, 2), 512, smem>>>(x);
    kan_out<<<(BB * 16) / 256, 256>>>(out);
}